// round 5
// baseline (speedup 1.0000x reference)
#include <cuda_runtime.h>

// ScaledDotProductAttention: B=4,H=16,S=2048,D=64 fp32, mask int32 [B,1,S,S].
// Outputs: out [B,H,S,D] followed by attn [B,H,S,S] in d_out (reference returns a tuple).

#define NB 4
#define NH 16
#define NS 2048
#define ND 64
#define ROWS 16          // q rows per CTA
#define CT 256           // k/v tile columns
#define NTH 512
#define NEGI (-1e14f)

__global__ __launch_bounds__(NTH, 1)
void sdpa_kernel(const float* __restrict__ Q, const float* __restrict__ K,
                 const float* __restrict__ V, const int* __restrict__ mask,
                 float* __restrict__ out, float* __restrict__ attn)
{
    extern __shared__ float sm[];
    float* sS  = sm;                   // ROWS*NS   = 32768 floats (128 KB) scores/P
    float* sKV = sS + ROWS * NS;       // CT*ND     = 16384 floats (64 KB)  K^T / V tile / reduce
    float* sQ  = sKV + CT * ND;        // ROWS*ND   = 1024 floats  (4 KB)   Q tile

    const int t  = threadIdx.x;
    const int bh = blockIdx.y;
    const int b  = bh >> 4;            // bh / NH
    const int q0 = blockIdx.x * ROWS;

    // ---- load Q tile (16x64) ----
    if (t < ROWS * ND / 4)
        ((float4*)sQ)[t] = ((const float4*)(Q + ((size_t)bh * NS + q0) * ND))[t];

    const int tx = t & 127;            // QK: col group
    const int ty = t >> 7;             // QK: row group (0..3)
    const int c0 = tx * 2;             // 2 local cols per thread
    const int lt = t & 15;             // loader: d-quad index
    const int ck = t >> 4;             // loader: base row/col (0..31)

    // =======================  Phase 1: scores = mask(scale * Q K^T)  =======================
    for (int ct = 0; ct < NS / CT; ++ct) {
        __syncthreads();               // previous tile fully consumed
        {   // load K tile [256 cols][64 d], stored d-major with XOR swizzle (d & 30)
            const float4* K4 = (const float4*)(K + ((size_t)bh * NS + (size_t)ct * CT) * ND);
            const int d0 = lt * 4;
            #pragma unroll
            for (int kk = 0; kk < 8; ++kk) {
                const int c = ck + kk * 32;
                float4 kv = K4[c * 16 + lt];
                sKV[(d0 + 0) * CT + (c ^ ((d0 + 0) & 30))] = kv.x;
                sKV[(d0 + 1) * CT + (c ^ ((d0 + 1) & 30))] = kv.y;
                sKV[(d0 + 2) * CT + (c ^ ((d0 + 2) & 30))] = kv.z;
                sKV[(d0 + 3) * CT + (c ^ ((d0 + 3) & 30))] = kv.w;
            }
        }
        __syncthreads();

        float a0[4], a1[4];
        #pragma unroll
        for (int rr = 0; rr < 4; ++rr) { a0[rr] = 0.f; a1[rr] = 0.f; }

        #pragma unroll
        for (int d4 = 0; d4 < 16; ++d4) {
            float qv[4][4];
            #pragma unroll
            for (int rr = 0; rr < 4; ++rr) {
                float4 qt = ((const float4*)sQ)[(ty * 4 + rr) * 16 + d4];
                qv[rr][0] = qt.x; qv[rr][1] = qt.y; qv[rr][2] = qt.z; qv[rr][3] = qt.w;
            }
            #pragma unroll
            for (int j = 0; j < 4; ++j) {
                const int dd = d4 * 4 + j;
                // c0 even, swizzle constant even -> the (c0, c0+1) pair stays adjacent
                const float2 kf = *(const float2*)&sKV[dd * CT + (c0 ^ (dd & 30))];
                #pragma unroll
                for (int rr = 0; rr < 4; ++rr) {
                    a0[rr] = fmaf(qv[rr][j], kf.x, a0[rr]);
                    a1[rr] = fmaf(qv[rr][j], kf.y, a1[rr]);
                }
            }
        }

        const int cg = ct * CT + c0;
        #pragma unroll
        for (int rr = 0; rr < 4; ++rr) {
            const int r = ty * 4 + rr;
            const int2 mm = *(const int2*)(mask + ((size_t)b * NS + (q0 + r)) * NS + cg);
            float2 sv;
            sv.x = (mm.x == 0) ? NEGI : a0[rr] * 0.125f;
            sv.y = (mm.y == 0) ? NEGI : a1[rr] * 0.125f;
            *(float2*)(sS + r * NS + cg) = sv;
        }
    }
    __syncthreads();

    // =======================  Phase 2: softmax, warp per row  =======================
    {
        const int w = t >> 5, l = t & 31;          // 16 warps == 16 rows
        float4 e[16];
        float mx = -3.4e38f;
        const float4* row4 = (const float4*)(sS + w * NS);
        #pragma unroll
        for (int i = 0; i < 16; ++i) {
            e[i] = row4[l + 32 * i];
            mx = fmaxf(mx, fmaxf(fmaxf(e[i].x, e[i].y), fmaxf(e[i].z, e[i].w)));
        }
        #pragma unroll
        for (int o = 16; o > 0; o >>= 1) mx = fmaxf(mx, __shfl_xor_sync(0xffffffffu, mx, o));
        float sum = 0.f;
        #pragma unroll
        for (int i = 0; i < 16; ++i) {
            e[i].x = __expf(e[i].x - mx);
            e[i].y = __expf(e[i].y - mx);
            e[i].z = __expf(e[i].z - mx);
            e[i].w = __expf(e[i].w - mx);
            sum += (e[i].x + e[i].y) + (e[i].z + e[i].w);
        }
        #pragma unroll
        for (int o = 16; o > 0; o >>= 1) sum += __shfl_xor_sync(0xffffffffu, sum, o);
        const float inv = 1.f / sum;
        float4* w4 = (float4*)(sS + w * NS);
        float4* a4 = attn ? (float4*)(attn + ((size_t)bh * NS + q0 + w) * NS) : (float4*)0;
        #pragma unroll
        for (int i = 0; i < 16; ++i) {
            float4 p = e[i];
            p.x *= inv; p.y *= inv; p.z *= inv; p.w *= inv;
            w4[l + 32 * i] = p;                    // normalized P back to smem (for PV)
            if (a4) a4[l + 32 * i] = p;            // attn output, coalesced float4
        }
    }

    // =======================  Phase 3: out = P @ V  =======================
    const int g  = t >> 7;        // k-quarter within each tile (0..3)
    const int u  = t & 127;
    const int ln = u & 31;        // d pair: d = 2*ln
    const int ry = u >> 5;        // row group (0..3): rows ry*4 .. ry*4+3
    float2 acc[4];
    #pragma unroll
    for (int rr = 0; rr < 4; ++rr) acc[rr] = make_float2(0.f, 0.f);

    for (int ct = 0; ct < NS / CT; ++ct) {
        __syncthreads();
        {   // load V tile [256 k][64 d], k-major (straight copy)
            const float4* V4 = (const float4*)(V + ((size_t)bh * NS + (size_t)ct * CT) * ND);
            #pragma unroll
            for (int kk = 0; kk < 8; ++kk) {
                const int k = ck + kk * 32;
                ((float4*)sKV)[k * 16 + lt] = V4[k * 16 + lt];
            }
        }
        __syncthreads();

        const int kb0 = g * 64;
        #pragma unroll 4
        for (int kb = 0; kb < 64; kb += 4) {
            const int k = kb0 + kb;
            float pv[4][4];
            #pragma unroll
            for (int rr = 0; rr < 4; ++rr) {
                float4 p = *(const float4*)(sS + (ry * 4 + rr) * NS + ct * CT + k);
                pv[rr][0] = p.x; pv[rr][1] = p.y; pv[rr][2] = p.z; pv[rr][3] = p.w;
            }
            #pragma unroll
            for (int j = 0; j < 4; ++j) {
                const float2 v = *(const float2*)(sKV + (k + j) * ND + ln * 2);
                #pragma unroll
                for (int rr = 0; rr < 4; ++rr) {
                    acc[rr].x = fmaf(pv[rr][j], v.x, acc[rr].x);
                    acc[rr].y = fmaf(pv[rr][j], v.y, acc[rr].y);
                }
            }
        }
    }

    // reduce the 4 k-quarter partials through smem, then store out
    __syncthreads();                                // everyone done reading sKV as V
    #pragma unroll
    for (int rr = 0; rr < 4; ++rr)
        *(float2*)(sKV + g * 1024 + (ry * 4 + rr) * ND + ln * 2) = acc[rr];
    __syncthreads();
    {
        const int i = t * 2;                        // 512 threads x 2 floats = 1024 outputs
        const int r = i >> 6;
        const int d = i & 63;
        float2 s = *(const float2*)(sKV + i);
        #pragma unroll
        for (int gg = 1; gg < 4; ++gg) {
            float2 v = *(const float2*)(sKV + gg * 1024 + i);
            s.x += v.x; s.y += v.y;
        }
        *(float2*)(out + ((size_t)bh * NS + q0 + r) * ND + d) = s;
    }
}

extern "C" void kernel_launch(void* const* d_in, const int* in_sizes, int n_in,
                              void* d_out, int out_size)
{
    const float* Q    = (const float*)d_in[0];
    const float* K    = (const float*)d_in[1];
    const float* V    = (const float*)d_in[2];
    const int*   mask = (const int*)d_in[3];
    float* out = (float*)d_out;

    const long long OUT_E  = (long long)NB * NH * NS * ND;           // 8388608
    const long long ATTN_E = (long long)NB * NH * NS * (long long)NS; // 268435456
    float* attn = ((long long)out_size >= OUT_E + ATTN_E) ? out + OUT_E : (float*)0;

    const int smem = (ROWS * NS + CT * ND + ROWS * ND) * (int)sizeof(float); // 200704 B
    cudaFuncSetAttribute(sdpa_kernel, cudaFuncAttributeMaxDynamicSharedMemorySize, smem);

    dim3 grid(NS / ROWS, NB * NH);   // q-tile fastest -> one head's 128 CTAs co-resident (L2 reuse of K/V/mask)
    sdpa_kernel<<<grid, NTH, smem>>>(Q, K, V, mask, out, attn);
}

// round 10
// speedup vs baseline: 1.0013x; 1.0013x over previous
#include <cuda_runtime.h>

// ScaledDotProductAttention: B=4,H=16,S=2048,D=64 fp32, mask int32 [B,1,S,S].
// Outputs: out [B,H,S,D] followed by attn [B,H,S,S] in d_out (reference returns a tuple).

#define NB 4
#define NH 16
#define NS 2048
#define ND 64
#define ROWS 16          // q rows per CTA
#define CT 256           // k/v tile columns
#define NTH 512
#define NEGI (-1e14f)

__global__ __launch_bounds__(NTH, 1)
void sdpa_kernel(const float* __restrict__ Q, const float* __restrict__ K,
                 const float* __restrict__ V, const int* __restrict__ mask,
                 float* __restrict__ out, float* __restrict__ attn)
{
    extern __shared__ float sm[];
    float* sS  = sm;                   // ROWS*NS   = 32768 floats (128 KB) scores/P
    float* sKV = sS + ROWS * NS;       // CT*ND     = 16384 floats (64 KB)  K^T / V tile / reduce
    float* sQ  = sKV + CT * ND;        // ROWS*ND   = 1024 floats  (4 KB)   Q tile

    const int t  = threadIdx.x;
    const int bh = blockIdx.y;
    const int b  = bh >> 4;            // bh / NH
    const int q0 = blockIdx.x * ROWS;

    // ---- load Q tile (16x64) ----
    if (t < ROWS * ND / 4)
        ((float4*)sQ)[t] = ((const float4*)(Q + ((size_t)bh * NS + q0) * ND))[t];

    const int tx = t & 127;            // QK: col group
    const int ty = t >> 7;             // QK: row group (0..3)
    const int c0 = tx * 2;             // 2 local cols per thread
    const int lt = t & 15;             // loader: d-quad index
    const int ck = t >> 4;             // loader: base row/col (0..31)

    // =======================  Phase 1: scores = mask(scale * Q K^T)  =======================
    for (int ct = 0; ct < NS / CT; ++ct) {
        __syncthreads();               // previous tile fully consumed
        {   // load K tile [256 cols][64 d], stored d-major with XOR swizzle (d & 30)
            const float4* K4 = (const float4*)(K + ((size_t)bh * NS + (size_t)ct * CT) * ND);
            const int d0 = lt * 4;
            #pragma unroll
            for (int kk = 0; kk < 8; ++kk) {
                const int c = ck + kk * 32;
                float4 kv = K4[c * 16 + lt];
                sKV[(d0 + 0) * CT + (c ^ ((d0 + 0) & 30))] = kv.x;
                sKV[(d0 + 1) * CT + (c ^ ((d0 + 1) & 30))] = kv.y;
                sKV[(d0 + 2) * CT + (c ^ ((d0 + 2) & 30))] = kv.z;
                sKV[(d0 + 3) * CT + (c ^ ((d0 + 3) & 30))] = kv.w;
            }
        }
        __syncthreads();

        float a0[4], a1[4];
        #pragma unroll
        for (int rr = 0; rr < 4; ++rr) { a0[rr] = 0.f; a1[rr] = 0.f; }

        #pragma unroll
        for (int d4 = 0; d4 < 16; ++d4) {
            float qv[4][4];
            #pragma unroll
            for (int rr = 0; rr < 4; ++rr) {
                float4 qt = ((const float4*)sQ)[(ty * 4 + rr) * 16 + d4];
                qv[rr][0] = qt.x; qv[rr][1] = qt.y; qv[rr][2] = qt.z; qv[rr][3] = qt.w;
            }
            #pragma unroll
            for (int j = 0; j < 4; ++j) {
                const int dd = d4 * 4 + j;
                // c0 even, swizzle constant even -> the (c0, c0+1) pair stays adjacent
                const float2 kf = *(const float2*)&sKV[dd * CT + (c0 ^ (dd & 30))];
                #pragma unroll
                for (int rr = 0; rr < 4; ++rr) {
                    a0[rr] = fmaf(qv[rr][j], kf.x, a0[rr]);
                    a1[rr] = fmaf(qv[rr][j], kf.y, a1[rr]);
                }
            }
        }

        const int cg = ct * CT + c0;
        #pragma unroll
        for (int rr = 0; rr < 4; ++rr) {
            const int r = ty * 4 + rr;
            const int2 mm = *(const int2*)(mask + ((size_t)b * NS + (q0 + r)) * NS + cg);
            float2 sv;
            sv.x = (mm.x == 0) ? NEGI : a0[rr] * 0.125f;
            sv.y = (mm.y == 0) ? NEGI : a1[rr] * 0.125f;
            *(float2*)(sS + r * NS + cg) = sv;
        }
    }
    __syncthreads();

    // =======================  Phase 2: softmax, warp per row  =======================
    {
        const int w = t >> 5, l = t & 31;          // 16 warps == 16 rows
        float4 e[16];
        float mx = -3.4e38f;
        const float4* row4 = (const float4*)(sS + w * NS);
        #pragma unroll
        for (int i = 0; i < 16; ++i) {
            e[i] = row4[l + 32 * i];
            mx = fmaxf(mx, fmaxf(fmaxf(e[i].x, e[i].y), fmaxf(e[i].z, e[i].w)));
        }
        #pragma unroll
        for (int o = 16; o > 0; o >>= 1) mx = fmaxf(mx, __shfl_xor_sync(0xffffffffu, mx, o));
        float sum = 0.f;
        #pragma unroll
        for (int i = 0; i < 16; ++i) {
            e[i].x = __expf(e[i].x - mx);
            e[i].y = __expf(e[i].y - mx);
            e[i].z = __expf(e[i].z - mx);
            e[i].w = __expf(e[i].w - mx);
            sum += (e[i].x + e[i].y) + (e[i].z + e[i].w);
        }
        #pragma unroll
        for (int o = 16; o > 0; o >>= 1) sum += __shfl_xor_sync(0xffffffffu, sum, o);
        const float inv = 1.f / sum;
        float4* w4 = (float4*)(sS + w * NS);
        float4* a4 = attn ? (float4*)(attn + ((size_t)bh * NS + q0 + w) * NS) : (float4*)0;
        #pragma unroll
        for (int i = 0; i < 16; ++i) {
            float4 p = e[i];
            p.x *= inv; p.y *= inv; p.z *= inv; p.w *= inv;
            w4[l + 32 * i] = p;                    // normalized P back to smem (for PV)
            if (a4) a4[l + 32 * i] = p;            // attn output, coalesced float4
        }
    }

    // =======================  Phase 3: out = P @ V  =======================
    const int g  = t >> 7;        // k-quarter within each tile (0..3)
    const int u  = t & 127;
    const int ln = u & 31;        // d pair: d = 2*ln
    const int ry = u >> 5;        // row group (0..3): rows ry*4 .. ry*4+3
    float2 acc[4];
    #pragma unroll
    for (int rr = 0; rr < 4; ++rr) acc[rr] = make_float2(0.f, 0.f);

    for (int ct = 0; ct < NS / CT; ++ct) {
        __syncthreads();
        {   // load V tile [256 k][64 d], k-major (straight copy)
            const float4* V4 = (const float4*)(V + ((size_t)bh * NS + (size_t)ct * CT) * ND);
            #pragma unroll
            for (int kk = 0; kk < 8; ++kk) {
                const int k = ck + kk * 32;
                ((float4*)sKV)[k * 16 + lt] = V4[k * 16 + lt];
            }
        }
        __syncthreads();

        const int kb0 = g * 64;
        #pragma unroll 4
        for (int kb = 0; kb < 64; kb += 4) {
            const int k = kb0 + kb;
            float pv[4][4];
            #pragma unroll
            for (int rr = 0; rr < 4; ++rr) {
                float4 p = *(const float4*)(sS + (ry * 4 + rr) * NS + ct * CT + k);
                pv[rr][0] = p.x; pv[rr][1] = p.y; pv[rr][2] = p.z; pv[rr][3] = p.w;
            }
            #pragma unroll
            for (int j = 0; j < 4; ++j) {
                const float2 v = *(const float2*)(sKV + (k + j) * ND + ln * 2);
                #pragma unroll
                for (int rr = 0; rr < 4; ++rr) {
                    acc[rr].x = fmaf(pv[rr][j], v.x, acc[rr].x);
                    acc[rr].y = fmaf(pv[rr][j], v.y, acc[rr].y);
                }
            }
        }
    }

    // reduce the 4 k-quarter partials through smem, then store out
    __syncthreads();                                // everyone done reading sKV as V
    #pragma unroll
    for (int rr = 0; rr < 4; ++rr)
        *(float2*)(sKV + g * 1024 + (ry * 4 + rr) * ND + ln * 2) = acc[rr];
    __syncthreads();
    {
        const int i = t * 2;                        // 512 threads x 2 floats = 1024 outputs
        const int r = i >> 6;
        const int d = i & 63;
        float2 s = *(const float2*)(sKV + i);
        #pragma unroll
        for (int gg = 1; gg < 4; ++gg) {
            float2 v = *(const float2*)(sKV + gg * 1024 + i);
            s.x += v.x; s.y += v.y;
        }
        *(float2*)(out + ((size_t)bh * NS + q0 + r) * ND + d) = s;
    }
}

extern "C" void kernel_launch(void* const* d_in, const int* in_sizes, int n_in,
                              void* d_out, int out_size)
{
    const float* Q    = (const float*)d_in[0];
    const float* K    = (const float*)d_in[1];
    const float* V    = (const float*)d_in[2];
    const int*   mask = (const int*)d_in[3];
    float* out = (float*)d_out;

    const long long OUT_E  = (long long)NB * NH * NS * ND;           // 8388608
    const long long ATTN_E = (long long)NB * NH * NS * (long long)NS; // 268435456
    float* attn = ((long long)out_size >= OUT_E + ATTN_E) ? out + OUT_E : (float*)0;

    const int smem = (ROWS * NS + CT * ND + ROWS * ND) * (int)sizeof(float); // 200704 B
    cudaFuncSetAttribute(sdpa_kernel, cudaFuncAttributeMaxDynamicSharedMemorySize, smem);

    dim3 grid(NS / ROWS, NB * NH);   // q-tile fastest -> one head's 128 CTAs co-resident (L2 reuse of K/V/mask)
    sdpa_kernel<<<grid, NTH, smem>>>(Q, K, V, mask, out, attn);
}

// round 11
// speedup vs baseline: 1.2003x; 1.1988x over previous
#include <cuda_runtime.h>

// ScaledDotProductAttention: B=4,H=16,S=2048,D=64 fp32, mask int32 [B,1,S,S].
// Outputs: out [B,H,S,D] followed by attn [B,H,S,S] in d_out.
//
// Register-resident scores: each thread holds 4 rows x 16 cols of the 16x2048
// score block. Shared memory only carries K tiles (swizzled, transposed),
// the transposed P matrix (swizzled), and V tiles.

#define NB 4
#define NH 16
#define NS 2048
#define ND 64
#define ROWS 16          // q rows per CTA
#define KT 512           // phase-1 K tile columns
#define VT 256           // phase-3 V tile rows
#define NTH 512
#define NEGI (-1e14f)

// smem layout (floats):
//  [0, 32768)        : sKP  — K tile (phase 1), then transposed P (phases 2-3), 128 KB
//  [32768, 49152)    : sV   — V tile (64 KB), reused as reduction buffer
//  [49152, 50176)    : sQ   — Q tile 16x64
//  [50176, 50240)    : sMx  — row-max partials (16 rows x 4 chunks)
//  [50240, 50304)    : sSm  — row-sum partials
#define SM_FLOATS 50304

__global__ __launch_bounds__(NTH, 1)
void sdpa_kernel(const float* __restrict__ Q, const float* __restrict__ K,
                 const float* __restrict__ V, const int* __restrict__ mask,
                 float* __restrict__ out, float* __restrict__ attn)
{
    extern __shared__ float sm[];
    float4* sKP = (float4*)sm;             // 8192 float4
    float4* sV4 = (float4*)(sm + 32768);   // 4096 float4
    float*  sQ  = sm + 49152;
    float*  sMx = sm + 50176;
    float*  sSm = sm + 50240;

    const int t  = threadIdx.x;
    const int bh = blockIdx.y;
    const int b  = bh >> 4;
    const int q0 = blockIdx.x * ROWS;

    // ---- Q tile (16x64) ----
    if (t < 256)
        ((float4*)sQ)[t] = ((const float4*)(Q + ((size_t)bh * NS + q0) * ND))[t];

    const int tx = t & 127;       // col-group: cols tx*4 .. tx*4+3 per tile
    const int ty = t >> 7;        // row-group: rows ty*4 .. ty*4+3

    // K loader indices
    const int ldq  = t & 15;      // d-quad (d = ldq*4 .. +3)
    const int lcb0 = t >> 4;      // c-block base (0..31)

    float s[4][16];               // scores: [row][tile*4 + cc]
    #pragma unroll
    for (int r = 0; r < 4; ++r)
        #pragma unroll
        for (int c = 0; c < 16; ++c) s[r][c] = 0.f;

    // =================== Phase 1: S = Q K^T (raw dots in regs) ===================
    #pragma unroll
    for (int tt = 0; tt < 4; ++tt) {
        __syncthreads();                       // previous K tile consumed
        {   // load K tile [KT cols][64 d], transpose via registers, swizzled d-major
            const float4* Kg = (const float4*)(K + ((size_t)bh * NS + (size_t)tt * KT) * ND);
            const int d0 = ldq * 4;
            #pragma unroll
            for (int i = 0; i < 4; ++i) {
                const int cb = lcb0 + 32 * i;
                float4 r0 = Kg[(cb * 4 + 0) * 16 + ldq];
                float4 r1 = Kg[(cb * 4 + 1) * 16 + ldq];
                float4 r2 = Kg[(cb * 4 + 2) * 16 + ldq];
                float4 r3 = Kg[(cb * 4 + 3) * 16 + ldq];
                sKP[(((d0 + 0) * 128 + cb) ^ (((d0 + 0) >> 2) & 7))] = make_float4(r0.x, r1.x, r2.x, r3.x);
                sKP[(((d0 + 1) * 128 + cb) ^ (((d0 + 1) >> 2) & 7))] = make_float4(r0.y, r1.y, r2.y, r3.y);
                sKP[(((d0 + 2) * 128 + cb) ^ (((d0 + 2) >> 2) & 7))] = make_float4(r0.z, r1.z, r2.z, r3.z);
                sKP[(((d0 + 3) * 128 + cb) ^ (((d0 + 3) >> 2) & 7))] = make_float4(r0.w, r1.w, r2.w, r3.w);
            }
        }
        __syncthreads();

        #pragma unroll 2
        for (int d4 = 0; d4 < 16; ++d4) {
            float qv[4][4];
            #pragma unroll
            for (int rr = 0; rr < 4; ++rr) {
                float4 qt = ((const float4*)sQ)[(ty * 4 + rr) * 16 + d4];   // broadcast
                qv[rr][0] = qt.x; qv[rr][1] = qt.y; qv[rr][2] = qt.z; qv[rr][3] = qt.w;
            }
            #pragma unroll
            for (int j = 0; j < 4; ++j) {
                const int d = d4 * 4 + j;
                const float4 kf = sKP[((d * 128 + tx) ^ ((d >> 2) & 7))];
                #pragma unroll
                for (int rr = 0; rr < 4; ++rr) {
                    s[rr][tt * 4 + 0] = fmaf(qv[rr][j], kf.x, s[rr][tt * 4 + 0]);
                    s[rr][tt * 4 + 1] = fmaf(qv[rr][j], kf.y, s[rr][tt * 4 + 1]);
                    s[rr][tt * 4 + 2] = fmaf(qv[rr][j], kf.z, s[rr][tt * 4 + 2]);
                    s[rr][tt * 4 + 3] = fmaf(qv[rr][j], kf.w, s[rr][tt * 4 + 3]);
                }
            }
        }
    }

    // =================== Phase 2: mask + softmax on registers ===================
    {
        // mask + scale
        #pragma unroll
        for (int rr = 0; rr < 4; ++rr) {
            const size_t mrow = ((size_t)b * NS + (q0 + ty * 4 + rr)) * NS;
            #pragma unroll
            for (int tt = 0; tt < 4; ++tt) {
                const int4 mm = *(const int4*)(mask + mrow + tt * KT + tx * 4);
                s[rr][tt * 4 + 0] = mm.x ? s[rr][tt * 4 + 0] * 0.125f : NEGI;
                s[rr][tt * 4 + 1] = mm.y ? s[rr][tt * 4 + 1] * 0.125f : NEGI;
                s[rr][tt * 4 + 2] = mm.z ? s[rr][tt * 4 + 2] * 0.125f : NEGI;
                s[rr][tt * 4 + 3] = mm.w ? s[rr][tt * 4 + 3] * 0.125f : NEGI;
            }
        }
        const int chunk = (t >> 5) & 3;
        // row max
        float mx[4];
        #pragma unroll
        for (int rr = 0; rr < 4; ++rr) {
            float m = s[rr][0];
            #pragma unroll
            for (int c = 1; c < 16; ++c) m = fmaxf(m, s[rr][c]);
            #pragma unroll
            for (int o = 16; o > 0; o >>= 1) m = fmaxf(m, __shfl_xor_sync(0xffffffffu, m, o));
            mx[rr] = m;
        }
        if ((t & 31) == 0)
            #pragma unroll
            for (int rr = 0; rr < 4; ++rr) sMx[(ty * 4 + rr) * 4 + chunk] = mx[rr];
        __syncthreads();
        float sum[4];
        #pragma unroll
        for (int rr = 0; rr < 4; ++rr) {
            const float* p = sMx + (ty * 4 + rr) * 4;
            const float rm = fmaxf(fmaxf(p[0], p[1]), fmaxf(p[2], p[3]));
            float su = 0.f;
            #pragma unroll
            for (int c = 0; c < 16; ++c) {
                s[rr][c] = __expf(s[rr][c] - rm);
                su += s[rr][c];
            }
            #pragma unroll
            for (int o = 16; o > 0; o >>= 1) su += __shfl_xor_sync(0xffffffffu, su, o);
            sum[rr] = su;
        }
        if ((t & 31) == 0)
            #pragma unroll
            for (int rr = 0; rr < 4; ++rr) sSm[(ty * 4 + rr) * 4 + chunk] = sum[rr];
        __syncthreads();   // also guarantees all phase-1 sKP reads are done
        #pragma unroll
        for (int rr = 0; rr < 4; ++rr) {
            const float* p = sSm + (ty * 4 + rr) * 4;
            const float inv = 1.f / (((p[0] + p[1]) + (p[2] + p[3])));
            #pragma unroll
            for (int c = 0; c < 16; ++c) s[rr][c] *= inv;
        }
        // write attn (coalesced float4)
        if (attn) {
            #pragma unroll
            for (int rr = 0; rr < 4; ++rr) {
                float* arow = attn + ((size_t)bh * NS + q0 + ty * 4 + rr) * NS;
                #pragma unroll
                for (int tt = 0; tt < 4; ++tt)
                    *(float4*)(arow + tt * KT + tx * 4) =
                        make_float4(s[rr][tt * 4 + 0], s[rr][tt * 4 + 1],
                                    s[rr][tt * 4 + 2], s[rr][tt * 4 + 3]);
            }
        }
        // write transposed P into sKP: sPt[k][16 rows], XOR-swizzled (4-wf stores = optimal)
        #pragma unroll
        for (int tt = 0; tt < 4; ++tt)
            #pragma unroll
            for (int j = 0; j < 4; ++j) {
                const int k = tt * KT + tx * 4 + j;
                sKP[((k * 4 + ty) ^ ((k >> 2) & 7))] =
                    make_float4(s[0][tt * 4 + j], s[1][tt * 4 + j],
                                s[2][tt * 4 + j], s[3][tt * 4 + j]);
            }
    }

    // =================== Phase 3: out = P @ V ===================
    const int g    = t >> 5;       // 16-way k-split, warp = g
    const int lane = t & 31;
    const int ry   = lane >> 3;    // rows ry*4 .. +3
    const int ln   = lane & 7;     // d slices: ln*4..+3 and 32+ln*4..+3
    float4 a0[4], a1[4];
    #pragma unroll
    for (int rr = 0; rr < 4; ++rr) {
        a0[rr] = make_float4(0.f, 0.f, 0.f, 0.f);
        a1[rr] = make_float4(0.f, 0.f, 0.f, 0.f);
    }

    for (int vt = 0; vt < NS / VT; ++vt) {
        __syncthreads();           // first iter: sPt written; later: prev V consumed
        {   // V tile [VT k][64 d], straight float4 copy
            const float4* Vg = (const float4*)(V + ((size_t)bh * NS + (size_t)vt * VT) * ND);
            #pragma unroll
            for (int i = 0; i < 8; ++i)
                sV4[t + 512 * i] = Vg[t + 512 * i];
        }
        __syncthreads();

        const int kbase = vt * VT + g * 16;
        #pragma unroll 4
        for (int kk = 0; kk < 16; ++kk) {
            const int k   = kbase + kk;
            const int ksm = k - vt * VT;
            const float4 p  = sKP[((k * 4 + ry) ^ ((k >> 2) & 7))];   // rows ry*4..+3 at col k
            const float4 v0 = sV4[ksm * 16 + ln];
            const float4 v1 = sV4[ksm * 16 + 8 + ln];
            const float pc[4] = {p.x, p.y, p.z, p.w};
            #pragma unroll
            for (int rr = 0; rr < 4; ++rr) {
                a0[rr].x = fmaf(pc[rr], v0.x, a0[rr].x);
                a0[rr].y = fmaf(pc[rr], v0.y, a0[rr].y);
                a0[rr].z = fmaf(pc[rr], v0.z, a0[rr].z);
                a0[rr].w = fmaf(pc[rr], v0.w, a0[rr].w);
                a1[rr].x = fmaf(pc[rr], v1.x, a1[rr].x);
                a1[rr].y = fmaf(pc[rr], v1.y, a1[rr].y);
                a1[rr].z = fmaf(pc[rr], v1.z, a1[rr].z);
                a1[rr].w = fmaf(pc[rr], v1.w, a1[rr].w);
            }
        }
    }

    // 16-way k-split reduction through smem (reuse sV region)
    __syncthreads();
    {
        float4* sR = sV4;          // [g][16 rows][16 float4-d]
        #pragma unroll
        for (int rr = 0; rr < 4; ++rr) {
            sR[g * 256 + (ry * 4 + rr) * 16 + ln]     = a0[rr];
            sR[g * 256 + (ry * 4 + rr) * 16 + 8 + ln] = a1[rr];
        }
    }
    __syncthreads();
    {
        const int o = t * 2;       // 1024 outputs, contiguous 16x64 tile
        const float* sR = (const float*)sV4;
        float2 acc = *(const float2*)(sR + o);
        #pragma unroll
        for (int gg = 1; gg < 16; ++gg) {
            const float2 v = *(const float2*)(sR + gg * 1024 + o);
            acc.x += v.x; acc.y += v.y;
        }
        *(float2*)(out + ((size_t)bh * NS + q0) * ND + o) = acc;
    }
}

extern "C" void kernel_launch(void* const* d_in, const int* in_sizes, int n_in,
                              void* d_out, int out_size)
{
    const float* Q    = (const float*)d_in[0];
    const float* K    = (const float*)d_in[1];
    const float* V    = (const float*)d_in[2];
    const int*   mask = (const int*)d_in[3];
    float* out = (float*)d_out;

    const long long OUT_E  = (long long)NB * NH * NS * ND;            // 8388608
    const long long ATTN_E = (long long)NB * NH * NS * (long long)NS; // 268435456
    float* attn = ((long long)out_size >= OUT_E + ATTN_E) ? out + OUT_E : (float*)0;

    const int smem = SM_FLOATS * (int)sizeof(float);   // 201216 B
    cudaFuncSetAttribute(sdpa_kernel, cudaFuncAttributeMaxDynamicSharedMemorySize, smem);

    dim3 grid(NS / ROWS, NB * NH);   // q-tile fastest -> one head's CTAs co-resident (L2 reuse)
    sdpa_kernel<<<grid, NTH, smem>>>(Q, K, V, mask, out, attn);
}

// round 12
// speedup vs baseline: 1.2014x; 1.0009x over previous
#include <cuda_runtime.h>

// ScaledDotProductAttention: B=4,H=16,S=2048,D=64 fp32, mask int32 [B,1,S,S].
// Outputs: out [B,H,S,D] followed by attn [B,H,S,S] in d_out.
//
// Register-resident scores: each thread holds 4 rows x 16 cols of the 16x2048
// score block. Shared memory only carries K tiles (swizzled, transposed),
// the transposed P matrix (swizzled), and V tiles.

#define NB 4
#define NH 16
#define NS 2048
#define ND 64
#define ROWS 16          // q rows per CTA
#define KT 512           // phase-1 K tile columns
#define VT 256           // phase-3 V tile rows
#define NTH 512
#define NEGI (-1e14f)

// smem layout (floats):
//  [0, 32768)        : sKP  — K tile (phase 1), then transposed P (phases 2-3), 128 KB
//  [32768, 49152)    : sV   — V tile (64 KB), reused as reduction buffer
//  [49152, 50176)    : sQ   — Q tile 16x64
//  [50176, 50240)    : sMx  — row-max partials (16 rows x 4 chunks)
//  [50240, 50304)    : sSm  — row-sum partials
#define SM_FLOATS 50304

__global__ __launch_bounds__(NTH, 1)
void sdpa_kernel(const float* __restrict__ Q, const float* __restrict__ K,
                 const float* __restrict__ V, const int* __restrict__ mask,
                 float* __restrict__ out, float* __restrict__ attn)
{
    extern __shared__ float sm[];
    float4* sKP = (float4*)sm;             // 8192 float4
    float4* sV4 = (float4*)(sm + 32768);   // 4096 float4
    float*  sQ  = sm + 49152;
    float*  sMx = sm + 50176;
    float*  sSm = sm + 50240;

    const int t  = threadIdx.x;
    const int bh = blockIdx.y;
    const int b  = bh >> 4;
    const int q0 = blockIdx.x * ROWS;

    // ---- Q tile (16x64) ----
    if (t < 256)
        ((float4*)sQ)[t] = ((const float4*)(Q + ((size_t)bh * NS + q0) * ND))[t];

    const int tx = t & 127;       // col-group: cols tx*4 .. tx*4+3 per tile
    const int ty = t >> 7;        // row-group: rows ty*4 .. ty*4+3

    // K loader indices
    const int ldq  = t & 15;      // d-quad (d = ldq*4 .. +3)
    const int lcb0 = t >> 4;      // c-block base (0..31)

    float s[4][16];               // scores: [row][tile*4 + cc]
    #pragma unroll
    for (int r = 0; r < 4; ++r)
        #pragma unroll
        for (int c = 0; c < 16; ++c) s[r][c] = 0.f;

    // =================== Phase 1: S = Q K^T (raw dots in regs) ===================
    #pragma unroll
    for (int tt = 0; tt < 4; ++tt) {
        __syncthreads();                       // previous K tile consumed
        {   // load K tile [KT cols][64 d], transpose via registers, swizzled d-major
            const float4* Kg = (const float4*)(K + ((size_t)bh * NS + (size_t)tt * KT) * ND);
            const int d0 = ldq * 4;
            #pragma unroll
            for (int i = 0; i < 4; ++i) {
                const int cb = lcb0 + 32 * i;
                float4 r0 = Kg[(cb * 4 + 0) * 16 + ldq];
                float4 r1 = Kg[(cb * 4 + 1) * 16 + ldq];
                float4 r2 = Kg[(cb * 4 + 2) * 16 + ldq];
                float4 r3 = Kg[(cb * 4 + 3) * 16 + ldq];
                sKP[(((d0 + 0) * 128 + cb) ^ (((d0 + 0) >> 2) & 7))] = make_float4(r0.x, r1.x, r2.x, r3.x);
                sKP[(((d0 + 1) * 128 + cb) ^ (((d0 + 1) >> 2) & 7))] = make_float4(r0.y, r1.y, r2.y, r3.y);
                sKP[(((d0 + 2) * 128 + cb) ^ (((d0 + 2) >> 2) & 7))] = make_float4(r0.z, r1.z, r2.z, r3.z);
                sKP[(((d0 + 3) * 128 + cb) ^ (((d0 + 3) >> 2) & 7))] = make_float4(r0.w, r1.w, r2.w, r3.w);
            }
        }
        __syncthreads();

        #pragma unroll 2
        for (int d4 = 0; d4 < 16; ++d4) {
            float qv[4][4];
            #pragma unroll
            for (int rr = 0; rr < 4; ++rr) {
                float4 qt = ((const float4*)sQ)[(ty * 4 + rr) * 16 + d4];   // broadcast
                qv[rr][0] = qt.x; qv[rr][1] = qt.y; qv[rr][2] = qt.z; qv[rr][3] = qt.w;
            }
            #pragma unroll
            for (int j = 0; j < 4; ++j) {
                const int d = d4 * 4 + j;
                const float4 kf = sKP[((d * 128 + tx) ^ ((d >> 2) & 7))];
                #pragma unroll
                for (int rr = 0; rr < 4; ++rr) {
                    s[rr][tt * 4 + 0] = fmaf(qv[rr][j], kf.x, s[rr][tt * 4 + 0]);
                    s[rr][tt * 4 + 1] = fmaf(qv[rr][j], kf.y, s[rr][tt * 4 + 1]);
                    s[rr][tt * 4 + 2] = fmaf(qv[rr][j], kf.z, s[rr][tt * 4 + 2]);
                    s[rr][tt * 4 + 3] = fmaf(qv[rr][j], kf.w, s[rr][tt * 4 + 3]);
                }
            }
        }
    }

    // =================== Phase 2: mask + softmax on registers ===================
    {
        // mask + scale
        #pragma unroll
        for (int rr = 0; rr < 4; ++rr) {
            const size_t mrow = ((size_t)b * NS + (q0 + ty * 4 + rr)) * NS;
            #pragma unroll
            for (int tt = 0; tt < 4; ++tt) {
                const int4 mm = *(const int4*)(mask + mrow + tt * KT + tx * 4);
                s[rr][tt * 4 + 0] = mm.x ? s[rr][tt * 4 + 0] * 0.125f : NEGI;
                s[rr][tt * 4 + 1] = mm.y ? s[rr][tt * 4 + 1] * 0.125f : NEGI;
                s[rr][tt * 4 + 2] = mm.z ? s[rr][tt * 4 + 2] * 0.125f : NEGI;
                s[rr][tt * 4 + 3] = mm.w ? s[rr][tt * 4 + 3] * 0.125f : NEGI;
            }
        }
        const int chunk = (t >> 5) & 3;
        // row max
        float mx[4];
        #pragma unroll
        for (int rr = 0; rr < 4; ++rr) {
            float m = s[rr][0];
            #pragma unroll
            for (int c = 1; c < 16; ++c) m = fmaxf(m, s[rr][c]);
            #pragma unroll
            for (int o = 16; o > 0; o >>= 1) m = fmaxf(m, __shfl_xor_sync(0xffffffffu, m, o));
            mx[rr] = m;
        }
        if ((t & 31) == 0)
            #pragma unroll
            for (int rr = 0; rr < 4; ++rr) sMx[(ty * 4 + rr) * 4 + chunk] = mx[rr];
        __syncthreads();
        float sum[4];
        #pragma unroll
        for (int rr = 0; rr < 4; ++rr) {
            const float* p = sMx + (ty * 4 + rr) * 4;
            const float rm = fmaxf(fmaxf(p[0], p[1]), fmaxf(p[2], p[3]));
            float su = 0.f;
            #pragma unroll
            for (int c = 0; c < 16; ++c) {
                s[rr][c] = __expf(s[rr][c] - rm);
                su += s[rr][c];
            }
            #pragma unroll
            for (int o = 16; o > 0; o >>= 1) su += __shfl_xor_sync(0xffffffffu, su, o);
            sum[rr] = su;
        }
        if ((t & 31) == 0)
            #pragma unroll
            for (int rr = 0; rr < 4; ++rr) sSm[(ty * 4 + rr) * 4 + chunk] = sum[rr];
        __syncthreads();   // also guarantees all phase-1 sKP reads are done
        #pragma unroll
        for (int rr = 0; rr < 4; ++rr) {
            const float* p = sSm + (ty * 4 + rr) * 4;
            const float inv = 1.f / (((p[0] + p[1]) + (p[2] + p[3])));
            #pragma unroll
            for (int c = 0; c < 16; ++c) s[rr][c] *= inv;
        }
        // write attn (coalesced float4)
        if (attn) {
            #pragma unroll
            for (int rr = 0; rr < 4; ++rr) {
                float* arow = attn + ((size_t)bh * NS + q0 + ty * 4 + rr) * NS;
                #pragma unroll
                for (int tt = 0; tt < 4; ++tt)
                    *(float4*)(arow + tt * KT + tx * 4) =
                        make_float4(s[rr][tt * 4 + 0], s[rr][tt * 4 + 1],
                                    s[rr][tt * 4 + 2], s[rr][tt * 4 + 3]);
            }
        }
        // write transposed P into sKP: sPt[k][16 rows], XOR-swizzled (4-wf stores = optimal)
        #pragma unroll
        for (int tt = 0; tt < 4; ++tt)
            #pragma unroll
            for (int j = 0; j < 4; ++j) {
                const int k = tt * KT + tx * 4 + j;
                sKP[((k * 4 + ty) ^ ((k >> 2) & 7))] =
                    make_float4(s[0][tt * 4 + j], s[1][tt * 4 + j],
                                s[2][tt * 4 + j], s[3][tt * 4 + j]);
            }
    }

    // =================== Phase 3: out = P @ V ===================
    const int g    = t >> 5;       // 16-way k-split, warp = g
    const int lane = t & 31;
    const int ry   = lane >> 3;    // rows ry*4 .. +3
    const int ln   = lane & 7;     // d slices: ln*4..+3 and 32+ln*4..+3
    float4 a0[4], a1[4];
    #pragma unroll
    for (int rr = 0; rr < 4; ++rr) {
        a0[rr] = make_float4(0.f, 0.f, 0.f, 0.f);
        a1[rr] = make_float4(0.f, 0.f, 0.f, 0.f);
    }

    for (int vt = 0; vt < NS / VT; ++vt) {
        __syncthreads();           // first iter: sPt written; later: prev V consumed
        {   // V tile [VT k][64 d], straight float4 copy
            const float4* Vg = (const float4*)(V + ((size_t)bh * NS + (size_t)vt * VT) * ND);
            #pragma unroll
            for (int i = 0; i < 8; ++i)
                sV4[t + 512 * i] = Vg[t + 512 * i];
        }
        __syncthreads();

        const int kbase = vt * VT + g * 16;
        #pragma unroll 4
        for (int kk = 0; kk < 16; ++kk) {
            const int k   = kbase + kk;
            const int ksm = k - vt * VT;
            const float4 p  = sKP[((k * 4 + ry) ^ ((k >> 2) & 7))];   // rows ry*4..+3 at col k
            const float4 v0 = sV4[ksm * 16 + ln];
            const float4 v1 = sV4[ksm * 16 + 8 + ln];
            const float pc[4] = {p.x, p.y, p.z, p.w};
            #pragma unroll
            for (int rr = 0; rr < 4; ++rr) {
                a0[rr].x = fmaf(pc[rr], v0.x, a0[rr].x);
                a0[rr].y = fmaf(pc[rr], v0.y, a0[rr].y);
                a0[rr].z = fmaf(pc[rr], v0.z, a0[rr].z);
                a0[rr].w = fmaf(pc[rr], v0.w, a0[rr].w);
                a1[rr].x = fmaf(pc[rr], v1.x, a1[rr].x);
                a1[rr].y = fmaf(pc[rr], v1.y, a1[rr].y);
                a1[rr].z = fmaf(pc[rr], v1.z, a1[rr].z);
                a1[rr].w = fmaf(pc[rr], v1.w, a1[rr].w);
            }
        }
    }

    // 16-way k-split reduction through smem (reuse sV region)
    __syncthreads();
    {
        float4* sR = sV4;          // [g][16 rows][16 float4-d]
        #pragma unroll
        for (int rr = 0; rr < 4; ++rr) {
            sR[g * 256 + (ry * 4 + rr) * 16 + ln]     = a0[rr];
            sR[g * 256 + (ry * 4 + rr) * 16 + 8 + ln] = a1[rr];
        }
    }
    __syncthreads();
    {
        const int o = t * 2;       // 1024 outputs, contiguous 16x64 tile
        const float* sR = (const float*)sV4;
        float2 acc = *(const float2*)(sR + o);
        #pragma unroll
        for (int gg = 1; gg < 16; ++gg) {
            const float2 v = *(const float2*)(sR + gg * 1024 + o);
            acc.x += v.x; acc.y += v.y;
        }
        *(float2*)(out + ((size_t)bh * NS + q0) * ND + o) = acc;
    }
}

extern "C" void kernel_launch(void* const* d_in, const int* in_sizes, int n_in,
                              void* d_out, int out_size)
{
    const float* Q    = (const float*)d_in[0];
    const float* K    = (const float*)d_in[1];
    const float* V    = (const float*)d_in[2];
    const int*   mask = (const int*)d_in[3];
    float* out = (float*)d_out;

    const long long OUT_E  = (long long)NB * NH * NS * ND;            // 8388608
    const long long ATTN_E = (long long)NB * NH * NS * (long long)NS; // 268435456
    float* attn = ((long long)out_size >= OUT_E + ATTN_E) ? out + OUT_E : (float*)0;

    const int smem = SM_FLOATS * (int)sizeof(float);   // 201216 B
    cudaFuncSetAttribute(sdpa_kernel, cudaFuncAttributeMaxDynamicSharedMemorySize, smem);

    dim3 grid(NS / ROWS, NB * NH);   // q-tile fastest -> one head's CTAs co-resident (L2 reuse)
    sdpa_kernel<<<grid, NTH, smem>>>(Q, K, V, mask, out, attn);
}

// round 16
// speedup vs baseline: 1.5045x; 1.2523x over previous
#include <cuda_runtime.h>
#include <cuda_bf16.h>
#include <cstdint>

// ScaledDotProductAttention B=4,H=16,S=2048,D=64 fp32 + int32 mask.
// Warp-level bf16 mma.sync (family-portable HMMA path) with 3-term hi/lo
// split precision on both GEMMs. CTA = 16 q rows x one (b,h), 16 warps.
// Pre-pass kernel converts K,V -> bf16 hi/lo global scratch once.

#define NB 4
#define NH 16
#define NS 2048
#define ND 64
#define NTH 512
#define NEGI (-1e14f)
#define ELEMS (NB*NH*NS*ND)          // 8388608

#define SWZ(o) ((o) ^ (((o) >> 3) & 0x70))

__device__ __nv_bfloat16 gKh[ELEMS];
__device__ __nv_bfloat16 gKl[ELEMS];
__device__ __nv_bfloat16 gVh[ELEMS];
__device__ __nv_bfloat16 gVl[ELEMS];

// ---- smem layout (bytes) ----
#define SB_S    0        // 64 KB stripe buffer: hi [0,32K), lo [32K,64K); reused for PV reduce
#define SB_QH   65536    // 2 KB  Q hi  (16 rows x 128 B, swizzled)
#define SB_QL   67584    // 2 KB  Q lo
#define SB_MAX  69632    // 1 KB  [16 warps][16 rows]
#define SB_SUM  70656    // 1 KB
#define SMEMB   71680

// ---------------- helpers ----------------
__device__ __forceinline__ uint32_t smem_u32(const void* p) {
    uint32_t a;
    asm("{ .reg .u64 t; cvta.to.shared.u64 t, %1; cvt.u32.u64 %0, t; }" : "=r"(a) : "l"(p));
    return a;
}
__device__ __forceinline__ void ldm_x4(uint32_t* r, uint32_t a) {
    asm volatile("ldmatrix.sync.aligned.m8n8.x4.shared.b16 {%0,%1,%2,%3}, [%4];"
        : "=r"(r[0]), "=r"(r[1]), "=r"(r[2]), "=r"(r[3]) : "r"(a));
}
__device__ __forceinline__ void ldm_x2(uint32_t* r, uint32_t a) {
    asm volatile("ldmatrix.sync.aligned.m8n8.x2.shared.b16 {%0,%1}, [%2];"
        : "=r"(r[0]), "=r"(r[1]) : "r"(a));
}
__device__ __forceinline__ void ldm_x2t(uint32_t* r, uint32_t a) {
    asm volatile("ldmatrix.sync.aligned.m8n8.x2.trans.shared.b16 {%0,%1}, [%2];"
        : "=r"(r[0]), "=r"(r[1]) : "r"(a));
}
__device__ __forceinline__ void mma16816(float* c, const uint32_t* a, const uint32_t* b) {
    asm volatile("mma.sync.aligned.m16n8k16.row.col.f32.bf16.bf16.f32 "
        "{%0,%1,%2,%3}, {%4,%5,%6,%7}, {%8,%9}, {%0,%1,%2,%3};"
        : "+f"(c[0]), "+f"(c[1]), "+f"(c[2]), "+f"(c[3])
        : "r"(a[0]), "r"(a[1]), "r"(a[2]), "r"(a[3]), "r"(b[0]), "r"(b[1]));
}
// pack (x,y) into bf16x2 hi and residual-lo (x -> low half)
__device__ __forceinline__ void split2(float x, float y, uint32_t& hi2, uint32_t& lo2) {
    const __nv_bfloat16 hx = __float2bfloat16_rn(x), hy = __float2bfloat16_rn(y);
    const float rx = x - __bfloat162float(hx), ry = y - __bfloat162float(hy);
    __nv_bfloat162 h; h.x = hx; h.y = hy;
    __nv_bfloat162 l; l.x = __float2bfloat16_rn(rx); l.y = __float2bfloat16_rn(ry);
    hi2 = *(uint32_t*)&h;
    lo2 = *(uint32_t*)&l;
}
__device__ __forceinline__ void split4(float4 v, uint2& hi, uint2& lo) {
    uint32_t h0, l0, h1, l1;
    split2(v.x, v.y, h0, l0);
    split2(v.z, v.w, h1, l1);
    hi = make_uint2(h0, h1);
    lo = make_uint2(l0, l1);
}

// ---------------- pre-pass: K,V fp32 -> bf16 hi/lo ----------------
__global__ __launch_bounds__(256, 4)
void conv_kv_kernel(const float* __restrict__ K, const float* __restrict__ V)
{
    const size_t i = (size_t)blockIdx.x * 256 + threadIdx.x;   // one float4 each
    uint2 h, l;
    split4(((const float4*)K)[i], h, l);
    ((uint2*)gKh)[i] = h;
    ((uint2*)gKl)[i] = l;
    split4(((const float4*)V)[i], h, l);
    ((uint2*)gVh)[i] = h;
    ((uint2*)gVl)[i] = l;
}

// ---------------- main kernel ----------------
__global__ __launch_bounds__(NTH, 1)
void sdpa_mma_kernel(const float* __restrict__ Q, const int* __restrict__ mask,
                     float* __restrict__ out, float* __restrict__ attn)
{
    extern __shared__ __align__(16) char smem[];
    const uint32_t sbase = smem_u32(smem);

    const int t    = threadIdx.x;
    const int w    = t >> 5;
    const int lane = t & 31;
    const int lr   = lane >> 2;     // fragment row (and +8)
    const int lq   = lane & 3;      // fragment col pair
    const int bh = blockIdx.y;
    const int b  = bh >> 4;
    const int q0 = blockIdx.x * 16;

    // ---- Q tile -> smem bf16 hi/lo, pre-scaled by 1/8 ----
    #pragma unroll
    for (int i = t; i < 1024; i += NTH) {
        const int row = i >> 6, d = i & 63;
        const float f = Q[((size_t)bh * NS + q0 + row) * ND + d] * 0.125f;
        const __nv_bfloat16 h = __float2bfloat16_rn(f);
        const float r = f - __bfloat162float(h);
        *(__nv_bfloat16*)(smem + SB_QH + SWZ(row * 128 + d * 2)) = h;
        *(__nv_bfloat16*)(smem + SB_QL + SWZ(row * 128 + d * 2)) = __float2bfloat16_rn(r);
    }
    __syncthreads();

    // ---- Q fragments (hoisted; identical across stripes) ----
    uint32_t qh[4][4], ql[4][4];
    {
        const int qrow = lane & 15, qhalf = lane >> 4;
        #pragma unroll
        for (int ks = 0; ks < 4; ++ks) {
            const uint32_t off = SWZ(qrow * 128 + ks * 32 + qhalf * 16);
            ldm_x4(qh[ks], sbase + SB_QH + off);
            ldm_x4(ql[ks], sbase + SB_QL + off);
        }
    }

    float sc[64];    // [stripe][ntile*4 + ci] : c0,c1 row lr; c2,c3 row lr+8

    // =============== Phase 1: S = Q K^T (bf16 3-term) ===============
    #pragma unroll
    for (int st = 0; st < 8; ++st) {
        __syncthreads();
        {   // stripe: K rows [st*256, st*256+256), hi+lo -> swizzled smem
            const size_t gbase = ((size_t)bh * NS + st * 256) * ND;
            #pragma unroll
            for (int j = 0; j < 4; ++j) {
                const int i = t + NTH * j;
                const int row = i >> 3, dg = i & 7;
                const size_t g = gbase + row * ND + dg * 8;
                const uint32_t so = SWZ(row * 128 + dg * 16);
                *(uint4*)(smem + SB_S + so)         = *(const uint4*)(gKh + g);
                *(uint4*)(smem + SB_S + 32768 + so) = *(const uint4*)(gKl + g);
            }
        }
        __syncthreads();

        #pragma unroll
        for (int nt = 0; nt < 2; ++nt) {
            float c[4] = {0.f, 0.f, 0.f, 0.f};
            const int n0 = w * 16 + nt * 8;
            #pragma unroll
            for (int ks = 0; ks < 4; ++ks) {
                const uint32_t ka = sbase + SB_S +
                    SWZ((n0 + (lane & 7)) * 128 + ks * 32 + ((lane >> 3) & 1) * 16);
                uint32_t kh2[2], kl2[2];
                ldm_x2(kh2, ka);
                ldm_x2(kl2, ka + 32768);
                mma16816(c, qh[ks], kh2);
                mma16816(c, qh[ks], kl2);
                mma16816(c, ql[ks], kh2);
            }
            // mask (scale already folded into Q)
            const int col = st * 256 + n0 + lq * 2;
            const int2 m0 = *(const int2*)(mask + ((size_t)b * NS + q0 + lr) * NS + col);
            const int2 m1 = *(const int2*)(mask + ((size_t)b * NS + q0 + lr + 8) * NS + col);
            sc[st * 8 + nt * 4 + 0] = m0.x ? c[0] : NEGI;
            sc[st * 8 + nt * 4 + 1] = m0.y ? c[1] : NEGI;
            sc[st * 8 + nt * 4 + 2] = m1.x ? c[2] : NEGI;
            sc[st * 8 + nt * 4 + 3] = m1.y ? c[3] : NEGI;
        }
    }

    // =============== Phase 2: softmax ===============
    float inv0, inv1, gm0, gm1;
    {
        float* sMax = (float*)(smem + SB_MAX);
        float* sSum = (float*)(smem + SB_SUM);
        float m0 = -3.4e38f, m1 = -3.4e38f;
        #pragma unroll
        for (int i = 0; i < 8; ++i) {
            #pragma unroll
            for (int nt = 0; nt < 2; ++nt) {
                m0 = fmaxf(m0, fmaxf(sc[i * 8 + nt * 4 + 0], sc[i * 8 + nt * 4 + 1]));
                m1 = fmaxf(m1, fmaxf(sc[i * 8 + nt * 4 + 2], sc[i * 8 + nt * 4 + 3]));
            }
        }
        #pragma unroll
        for (int o = 1; o <= 2; o <<= 1) {
            m0 = fmaxf(m0, __shfl_xor_sync(0xffffffffu, m0, o));
            m1 = fmaxf(m1, __shfl_xor_sync(0xffffffffu, m1, o));
        }
        if (lq == 0) { sMax[w * 16 + lr] = m0; sMax[w * 16 + lr + 8] = m1; }
        __syncthreads();
        gm0 = sMax[lr]; gm1 = sMax[lr + 8];
        #pragma unroll
        for (int w1 = 1; w1 < 16; ++w1) {
            gm0 = fmaxf(gm0, sMax[w1 * 16 + lr]);
            gm1 = fmaxf(gm1, sMax[w1 * 16 + lr + 8]);
        }
        float s0 = 0.f, s1 = 0.f;
        #pragma unroll
        for (int i = 0; i < 8; ++i) {
            #pragma unroll
            for (int nt = 0; nt < 2; ++nt) {
                float e0 = __expf(sc[i * 8 + nt * 4 + 0] - gm0);
                float e1 = __expf(sc[i * 8 + nt * 4 + 1] - gm0);
                float e2 = __expf(sc[i * 8 + nt * 4 + 2] - gm1);
                float e3 = __expf(sc[i * 8 + nt * 4 + 3] - gm1);
                sc[i * 8 + nt * 4 + 0] = e0; sc[i * 8 + nt * 4 + 1] = e1;
                sc[i * 8 + nt * 4 + 2] = e2; sc[i * 8 + nt * 4 + 3] = e3;
                s0 += e0 + e1; s1 += e2 + e3;
            }
        }
        #pragma unroll
        for (int o = 1; o <= 2; o <<= 1) {
            s0 += __shfl_xor_sync(0xffffffffu, s0, o);
            s1 += __shfl_xor_sync(0xffffffffu, s1, o);
        }
        if (lq == 0) { sSum[w * 16 + lr] = s0; sSum[w * 16 + lr + 8] = s1; }
        __syncthreads();
        float l0 = 0.f, l1 = 0.f;
        #pragma unroll
        for (int w1 = 0; w1 < 16; ++w1) {
            l0 += sSum[w1 * 16 + lr];
            l1 += sSum[w1 * 16 + lr + 8];
        }
        inv0 = 1.f / l0;
        inv1 = 1.f / l1;
    }

    // =============== Phase 3: attn write + O = P V (bf16 3-term) ===============
    float oc[8][4];
    #pragma unroll
    for (int nd = 0; nd < 8; ++nd)
        #pragma unroll
        for (int ci = 0; ci < 4; ++ci) oc[nd][ci] = 0.f;

    #pragma unroll
    for (int st = 0; st < 8; ++st) {
        // normalize this stripe's P, write attn, build A-fragments
        const float p00 = sc[st * 8 + 0] * inv0, p01 = sc[st * 8 + 1] * inv0;
        const float p10 = sc[st * 8 + 2] * inv1, p11 = sc[st * 8 + 3] * inv1;
        const float r00 = sc[st * 8 + 4] * inv0, r01 = sc[st * 8 + 5] * inv0;
        const float r10 = sc[st * 8 + 6] * inv1, r11 = sc[st * 8 + 7] * inv1;
        uint32_t ah[4], al[4];
        split2(p00, p01, ah[0], al[0]);   // row lr,   k 0-7 half (ntile0)
        split2(p10, p11, ah[1], al[1]);   // row lr+8, k 0-7 half
        split2(r00, r01, ah[2], al[2]);   // row lr,   k 8-15 half (ntile1)
        split2(r10, r11, ah[3], al[3]);   // row lr+8, k 8-15 half
        if (attn) {
            float* a0p = attn + ((size_t)bh * NS + q0 + lr) * NS + st * 256 + w * 16 + lq * 2;
            float* a1p = a0p + 8 * NS;
            *(float2*)(a0p)     = make_float2(p00, p01);
            *(float2*)(a0p + 8) = make_float2(r00, r01);
            *(float2*)(a1p)     = make_float2(p10, p11);
            *(float2*)(a1p + 8) = make_float2(r10, r11);
        }

        __syncthreads();                  // everyone done with previous stripe buffer
        {   // V stripe hi/lo -> swizzled smem
            const size_t gbase = ((size_t)bh * NS + st * 256) * ND;
            #pragma unroll
            for (int j = 0; j < 4; ++j) {
                const int i = t + NTH * j;
                const int row = i >> 3, dg = i & 7;
                const size_t g = gbase + row * ND + dg * 8;
                const uint32_t so = SWZ(row * 128 + dg * 16);
                *(uint4*)(smem + SB_S + so)         = *(const uint4*)(gVh + g);
                *(uint4*)(smem + SB_S + 32768 + so) = *(const uint4*)(gVl + g);
            }
        }
        __syncthreads();

        #pragma unroll
        for (int nd = 0; nd < 8; ++nd) {
            const uint32_t va = sbase + SB_S + SWZ((w * 16 + (lane & 15)) * 128 + nd * 16);
            uint32_t vh2[2], vl2[2];
            ldm_x2t(vh2, va);
            ldm_x2t(vl2, va + 32768);
            mma16816(oc[nd], ah, vh2);
            mma16816(oc[nd], ah, vl2);
            mma16816(oc[nd], al, vh2);
        }
    }

    // =============== cross-warp k-split reduction + out ===============
    __syncthreads();
    {
        float* red = (float*)(smem + SB_S);   // [16 warps][16 rows][64 d]
        #pragma unroll
        for (int nd = 0; nd < 8; ++nd) {
            const int base = w * 1024 + lr * 64 + nd * 8 + lq * 2;
            *(float2*)(red + base)           = make_float2(oc[nd][0], oc[nd][1]);
            *(float2*)(red + base + 8 * 64)  = make_float2(oc[nd][2], oc[nd][3]);
        }
    }
    __syncthreads();
    {
        const float* red = (const float*)(smem + SB_S);
        const int o = t * 2;
        const int row = o >> 6, d = o & 63;
        float2 acc = *(const float2*)(red + o);
        #pragma unroll
        for (int w1 = 1; w1 < 16; ++w1) {
            const float2 v = *(const float2*)(red + w1 * 1024 + o);
            acc.x += v.x; acc.y += v.y;
        }
        *(float2*)(out + ((size_t)bh * NS + q0 + row) * ND + d) = acc;
    }
}

extern "C" void kernel_launch(void* const* d_in, const int* in_sizes, int n_in,
                              void* d_out, int out_size)
{
    const float* Q    = (const float*)d_in[0];
    const float* K    = (const float*)d_in[1];
    const float* V    = (const float*)d_in[2];
    const int*   mask = (const int*)d_in[3];
    float* out = (float*)d_out;

    const long long OUT_E  = (long long)NB * NH * NS * ND;            // 8388608
    const long long ATTN_E = (long long)NB * NH * NS * (long long)NS; // 268435456
    float* attn = ((long long)out_size >= OUT_E + ATTN_E) ? out + OUT_E : (float*)0;

    // pre-pass: K,V -> bf16 hi/lo scratch
    conv_kv_kernel<<<ELEMS / 4 / 256, 256>>>(K, V);

    cudaFuncSetAttribute(sdpa_mma_kernel, cudaFuncAttributeMaxDynamicSharedMemorySize, SMEMB);
    dim3 grid(NS / 16, NB * NH);   // 128 x 64, q-tile fastest for L2 reuse of K/V/mask
    sdpa_mma_kernel<<<grid, NTH, SMEMB>>>(Q, mask, out, attn);
}